// round 15
// baseline (speedup 1.0000x reference)
#include <cuda_runtime.h>
#include <stdint.h>
#include <math.h>

#define EPSF 1e-3f

// ---------------- scratch (allocation-free: __device__ globals) ----------------
__device__ __align__(1024) float g_imgT[64UL * 1600UL * 256UL];  // [F][H*W][C]
__device__ __align__(1024) float g_A  [4096UL * 12544UL];   // im2col  [R][bin*256+c], tf32-rounded
__device__ __align__(1024) float g_W1p[ 512UL * 12544UL];   // w1 perm [O][bin*256+c], tf32-rounded
__device__ __align__(1024) float g_W2r[ 512UL *   512UL];   // tf32-rounded w2
__device__ __align__(1024) float g_H1 [4096UL *   512UL];   // tf32-rounded FC1 out
__device__ __align__(1024) float g_H2 [4096UL *   512UL];

__device__ __forceinline__ float tf32r(float x) {
    uint32_t u;
    asm("cvt.rna.tf32.f32 %0, %1;" : "=r"(u) : "f"(x));
    return __uint_as_float(u);
}

// ------------------------------------------------------------------
// Transpose images [F,C,1600] -> [F,1600,C].
// ------------------------------------------------------------------
__global__ void transpose_img_kernel(const float* __restrict__ images) {
    __shared__ float tile[32][33];
    const int f   = blockIdx.z;
    const int hw0 = blockIdx.x * 32;
    const int c0  = blockIdx.y * 32;
    const float* src = images + (size_t)f * 256 * 1600;
    float*       dst = g_imgT + (size_t)f * 1600 * 256;

    #pragma unroll
    for (int i = 0; i < 4; ++i) {
        const int c = c0 + threadIdx.y + i * 8;
        tile[threadIdx.y + i * 8][threadIdx.x] = src[(size_t)c * 1600 + hw0 + threadIdx.x];
    }
    __syncthreads();
    #pragma unroll
    for (int i = 0; i < 4; ++i) {
        const int hw = hw0 + threadIdx.y + i * 8;
        dst[(size_t)hw * 256 + c0 + threadIdx.x] = tile[threadIdx.x][threadIdx.y + i * 8];
    }
}

// ------------------------------------------------------------------
// Permute + tf32-round w1 [O=512, C=256, 49] -> [O][bin*256+c]
// ------------------------------------------------------------------
__global__ void permute_w1_kernel(const float* __restrict__ w1) {
    __shared__ float buf[128 * 49];
    const int o  = blockIdx.x >> 1;
    const int c0 = (blockIdx.x & 1) * 128;
    const float* src = w1 + (size_t)o * 12544 + (size_t)c0 * 49;
    for (int i = threadIdx.x; i < 128 * 49; i += 256) buf[i] = src[i];
    __syncthreads();
    float* dst = g_W1p + (size_t)o * 12544;
    for (int i = threadIdx.x; i < 128 * 49; i += 256) {
        const int bin = i >> 7;
        const int cc  = i & 127;
        dst[bin * 256 + c0 + cc] = tf32r(buf[cc * 49 + bin]);
    }
}

__global__ void round_w2_kernel(const float* __restrict__ w2) {
    const int i = blockIdx.x * 256 + threadIdx.x;
    g_W2r[i] = tf32r(w2[i]);
}

// ------------------------------------------------------------------
// RoIAlign + im2col, 4 channels per thread (float4), 64 thr/block.
// ------------------------------------------------------------------
__global__ __launch_bounds__(64) void roi_im2col_kernel(const int*   __restrict__ kfi,
                                                        const float* __restrict__ boxes) {
    const int r  = blockIdx.x;
    const int c4 = threadIdx.x;          // channel quad 0..63

    const int f = kfi[r];
    const float x1 = boxes[r * 4 + 0] * 40.0f;
    const float y1 = boxes[r * 4 + 1] * 40.0f;
    const float x2 = boxes[r * 4 + 2] * 40.0f;
    const float y2 = boxes[r * 4 + 3] * 40.0f;
    const float bw = (x2 - x1) / 7.0f;
    const float bh = (y2 - y1) / 7.0f;

    const float4* __restrict__ img =
        (const float4*)(g_imgT + (size_t)f * 1600 * 256) + c4;
    float4* __restrict__ arow = (float4*)(g_A + (size_t)r * 12544) + c4;

    #pragma unroll 7
    for (int bin = 0; bin < 49; ++bin) {
        const int by = bin / 7;
        const int bx = bin - by * 7;
        const float X = x1 + ((float)bx + 0.5f) * bw;
        const float Y = y1 + ((float)by + 0.5f) * bh;
        const bool valid = (X > -1.0f) && (X < 40.0f) && (Y > -1.0f) && (Y < 40.0f);

        float x = fminf(fmaxf(X, 0.0f), 39.0f);
        float y = fminf(fmaxf(Y, 0.0f), 39.0f);
        const int x0 = (int)floorf(x);
        const int y0 = (int)floorf(y);
        const int x1i = min(x0 + 1, 39);
        const int y1i = min(y0 + 1, 39);
        const float lx = x - (float)x0;
        const float ly = y - (float)y0;

        float4 v = make_float4(0.0f, 0.0f, 0.0f, 0.0f);
        if (valid) {
            const float w00 = (1.0f - ly) * (1.0f - lx);
            const float w01 = (1.0f - ly) * lx;
            const float w10 = ly * (1.0f - lx);
            const float w11 = ly * lx;
            const float4 p00 = img[(size_t)(y0  * 40 + x0 ) * 64];
            const float4 p01 = img[(size_t)(y0  * 40 + x1i) * 64];
            const float4 p10 = img[(size_t)(y1i * 40 + x0 ) * 64];
            const float4 p11 = img[(size_t)(y1i * 40 + x1i) * 64];
            v.x = p00.x * w00 + p01.x * w01 + p10.x * w10 + p11.x * w11;
            v.y = p00.y * w00 + p01.y * w01 + p10.y * w10 + p11.y * w11;
            v.z = p00.z * w00 + p01.z * w01 + p10.z * w10 + p11.z * w11;
            v.w = p00.w * w00 + p01.w * w01 + p10.w * w10 + p11.w * w11;
        }
        arow[bin * 64] = make_float4(tf32r(v.x), tf32r(v.y), tf32r(v.z), tf32r(v.w));
    }
}

// ------------------------------------------------------------------
// tf32 mma.sync GEMM v5: 2 CTAs/SM for inter-CTA latency hiding.
// BM=64, BN=128, BK=32, 256 threads (8 warps, 2x4), warp tile 32x32.
// 4-stage cp.async pipeline (24KB/stage, 97KB total), LDSM frags.
// grid 64x4 = 256 CTAs -> single wave at 2 CTAs/SM on 148 SMs.
// ------------------------------------------------------------------
#define STAGES 4
#define STAGE_FLOATS 6144                 // A 2048 + B 4096
#define GEMM_SMEM_BYTES (STAGES * STAGE_FLOATS * 4 + 1024)   // 99328

__device__ __forceinline__ void cpasync16(uint32_t s, const float* g) {
    asm volatile("cp.async.cg.shared.global [%0], [%1], 16;" :: "r"(s), "l"(g) : "memory");
}
__device__ __forceinline__ void mma_tf32(float* d, const uint32_t* a, const uint32_t* b) {
    asm volatile("mma.sync.aligned.m16n8k8.row.col.f32.tf32.tf32.f32 "
                 "{%0,%1,%2,%3}, {%4,%5,%6,%7}, {%8,%9}, {%0,%1,%2,%3};"
                 : "+f"(d[0]), "+f"(d[1]), "+f"(d[2]), "+f"(d[3])
                 : "r"(a[0]), "r"(a[1]), "r"(a[2]), "r"(a[3]), "r"(b[0]), "r"(b[1]));
}
__device__ __forceinline__ void ldsm_x4(uint32_t* d, uint32_t addr) {
    asm volatile("ldmatrix.sync.aligned.m8n8.x4.shared.b16 {%0,%1,%2,%3}, [%4];"
                 : "=r"(d[0]), "=r"(d[1]), "=r"(d[2]), "=r"(d[3]) : "r"(addr));
}

__global__ __launch_bounds__(256, 2) void gemm_mma_kernel(
    const float* __restrict__ A, const float* __restrict__ B,
    float* __restrict__ C, int K,
    const float* __restrict__ bias,
    const float* __restrict__ gamma, const float* __restrict__ beta,
    const float* __restrict__ mean,  const float* __restrict__ var,
    int round_out)
{
    extern __shared__ float smem[];
    float* sarr = smem + STAGES * STAGE_FLOATS;
    float* oarr = sarr + 128;

    const int t    = threadIdx.x;
    const int lane = t & 31;
    const int wid  = t >> 5;
    const int mw   = wid & 1;          // 0..1 (M, x32)
    const int nw   = wid >> 1;         // 0..3 (N, x32)
    const int g    = lane >> 2;
    const int tig  = lane & 3;
    const int bm   = blockIdx.x * 64;
    const int bn   = blockIdx.y * 128;

    for (int c2 = t; c2 < 128; c2 += 256) {
        const int cg = bn + c2;
        const float s = gamma[cg] * rsqrtf(var[cg] + EPSF);
        sarr[c2] = s;
        oarr[c2] = (bias[cg] - mean[cg]) * s + beta[cg];
    }

    uint32_t sbase;
    asm("{ .reg .u64 t0; cvta.to.shared.u64 t0, %1; cvt.u32.u64 %0, t0; }"
        : "=r"(sbase) : "l"(smem));

    // ldmatrix per-lane addressing (A: 64 rows, B: 128 rows; 128B/row):
    const int rr   = lane & 7;
    const int rowa = mw * 32 + rr + ((lane >> 3) & 1) * 8;      // + mf*16
    const int qha  = (lane >> 4) & 1;
    const uint32_t aoff = (uint32_t)rowa * 128;
    const uint32_t swa  = (uint32_t)(rowa & 7);
    const int rowb = nw * 32 + rr + ((lane >> 4) & 1) * 8;      // + j*16
    const int qhb  = (lane >> 3) & 1;
    const uint32_t boff = (uint32_t)rowb * 128 + 2048 * 4;      // B after A (8 KB)
    const uint32_t swb  = (uint32_t)(rowb & 7);

    // cp.async chunk plan: A 512 chunks (2/thread), B 1024 chunks (4/thread)
    const float* aG[2]; uint32_t aS[2];
    const float* bG[4]; uint32_t bS[4];
    #pragma unroll
    for (int j = 0; j < 2; ++j) {
        const int id = t + j * 256;       // 0..511
        const int m  = id >> 3;           // row 0..63
        const int cc = id & 7;
        aG[j] = A + (size_t)(bm + m) * K + cc * 4;
        aS[j] = (uint32_t)(m * 32 + ((cc ^ (m & 7)) << 2)) * 4;
    }
    #pragma unroll
    for (int j = 0; j < 4; ++j) {
        const int id = t + j * 256;       // 0..1023
        const int m  = id >> 3;           // row 0..127
        const int cc = id & 7;
        bG[j] = B + (size_t)(bn + m) * K + cc * 4;
        bS[j] = (uint32_t)(m * 32 + ((cc ^ (m & 7)) << 2)) * 4 + 2048 * 4;
    }

    const int nkt = K >> 5;

    const int npre = nkt < 3 ? nkt : 3;
    for (int s = 0; s < npre; ++s) {
        const uint32_t stg = sbase + s * (STAGE_FLOATS * 4);
        #pragma unroll
        for (int j = 0; j < 2; ++j) cpasync16(stg + aS[j], aG[j] + s * 32);
        #pragma unroll
        for (int j = 0; j < 4; ++j) cpasync16(stg + bS[j], bG[j] + s * 32);
        asm volatile("cp.async.commit_group;" ::: "memory");
    }

    float acc[2][4][4];
    #pragma unroll
    for (int i = 0; i < 2; ++i)
        #pragma unroll
        for (int j = 0; j < 4; ++j)
            #pragma unroll
            for (int q = 0; q < 4; ++q) acc[i][j][q] = 0.0f;

    for (int kt = 0; kt < nkt; ++kt) {
        const int st = kt & (STAGES - 1);
        asm volatile("cp.async.wait_group 2;" ::: "memory");
        __syncthreads();

        const int kp = kt + 3;
        if (kp < nkt) {
            const int sp = kp & (STAGES - 1);
            const uint32_t stg = sbase + sp * (STAGE_FLOATS * 4);
            #pragma unroll
            for (int j = 0; j < 2; ++j) cpasync16(stg + aS[j], aG[j] + kp * 32);
            #pragma unroll
            for (int j = 0; j < 4; ++j) cpasync16(stg + bS[j], bG[j] + kp * 32);
        }
        asm volatile("cp.async.commit_group;" ::: "memory");

        const uint32_t sAb = sbase + st * (STAGE_FLOATS * 4);

        #pragma unroll
        for (int kk = 0; kk < 4; ++kk) {
            uint32_t afr[2][4], bfr[4][2];
            const uint32_t ach = ((uint32_t)(2 * kk + qha) ^ swa) << 4;
            const uint32_t bch = ((uint32_t)(2 * kk + qhb) ^ swb) << 4;
            #pragma unroll
            for (int mf = 0; mf < 2; ++mf)
                ldsm_x4(afr[mf], sAb + aoff + (uint32_t)mf * 2048 + ach);
            #pragma unroll
            for (int j = 0; j < 2; ++j) {
                uint32_t d4[4];
                ldsm_x4(d4, sAb + boff + (uint32_t)j * 2048 + bch);
                bfr[2 * j][0]     = d4[0];
                bfr[2 * j][1]     = d4[1];
                bfr[2 * j + 1][0] = d4[2];
                bfr[2 * j + 1][1] = d4[3];
            }
            #pragma unroll
            for (int mf = 0; mf < 2; ++mf)
                #pragma unroll
                for (int nf = 0; nf < 4; ++nf)
                    mma_tf32(acc[mf][nf], afr[mf], bfr[nf]);
        }
    }

    // epilogue: bias+BN+ReLU (+optional tf32 rounding), float2 stores
    #pragma unroll
    for (int mf = 0; mf < 2; ++mf) {
        const int r0 = bm + mw * 32 + mf * 16 + g;
        #pragma unroll
        for (int nf = 0; nf < 4; ++nf) {
            const int cl = nw * 32 + nf * 8 + tig * 2;
            const float s0 = sarr[cl],     s1 = sarr[cl + 1];
            const float o0 = oarr[cl],     o1 = oarr[cl + 1];
            float v00 = fmaxf(acc[mf][nf][0] * s0 + o0, 0.0f);
            float v01 = fmaxf(acc[mf][nf][1] * s1 + o1, 0.0f);
            float v10 = fmaxf(acc[mf][nf][2] * s0 + o0, 0.0f);
            float v11 = fmaxf(acc[mf][nf][3] * s1 + o1, 0.0f);
            if (round_out) {
                v00 = tf32r(v00); v01 = tf32r(v01);
                v10 = tf32r(v10); v11 = tf32r(v11);
            }
            *(float2*)(C + (size_t)r0 * 512 + bn + cl)       = make_float2(v00, v01);
            *(float2*)(C + (size_t)(r0 + 8) * 512 + bn + cl) = make_float2(v10, v11);
        }
    }
}

// ------------------------------------------------------------------
// max over K=8 keyframes
// ------------------------------------------------------------------
__global__ void max_k_kernel(const float* __restrict__ H2, float* __restrict__ out) {
    const int n = blockIdx.x;
    const int d = threadIdx.x;
    const float* p = H2 + (size_t)n * 8 * 512 + d;
    float m = p[0];
    #pragma unroll
    for (int k = 1; k < 8; ++k) m = fmaxf(m, p[(size_t)k * 512]);
    out[(size_t)n * 512 + d] = m;
}

// ------------------------------------------------------------------
extern "C" void kernel_launch(void* const* d_in, const int* in_sizes, int n_in,
                              void* d_out, int out_size) {
    const float* images = (const float*)d_in[0];
    const int*   kfi    = (const int*)  d_in[1];
    const float* boxes  = (const float*)d_in[2];
    const float* w1     = (const float*)d_in[3];
    const float* b1     = (const float*)d_in[4];
    const float* g1     = (const float*)d_in[5];
    const float* bt1    = (const float*)d_in[6];
    const float* m1     = (const float*)d_in[7];
    const float* v1     = (const float*)d_in[8];
    const float* w2     = (const float*)d_in[9];
    const float* b2     = (const float*)d_in[10];
    const float* g2     = (const float*)d_in[11];
    const float* bt2    = (const float*)d_in[12];
    const float* m2     = (const float*)d_in[13];
    const float* v2     = (const float*)d_in[14];

    float *A, *W1p, *W2r, *H1, *H2;
    cudaGetSymbolAddress((void**)&A,   g_A);
    cudaGetSymbolAddress((void**)&W1p, g_W1p);
    cudaGetSymbolAddress((void**)&W2r, g_W2r);
    cudaGetSymbolAddress((void**)&H1,  g_H1);
    cudaGetSymbolAddress((void**)&H2,  g_H2);

    cudaFuncSetAttribute(gemm_mma_kernel, cudaFuncAttributeMaxDynamicSharedMemorySize,
                         GEMM_SMEM_BYTES);

    // prep (independent, cheap)
    transpose_img_kernel<<<dim3(50, 8, 64), dim3(32, 8)>>>(images);
    permute_w1_kernel<<<1024, 256>>>(w1);
    round_w2_kernel<<<1024, 256>>>(w2);

    // roi-align im2col from channel-last layout
    roi_im2col_kernel<<<4096, 64>>>(kfi, boxes);

    // FC1
    gemm_mma_kernel<<<dim3(64, 4), 256, GEMM_SMEM_BYTES>>>(A, W1p, H1, 12544,
                                                           b1, g1, bt1, m1, v1, 1);
    // FC2
    gemm_mma_kernel<<<dim3(64, 4), 256, GEMM_SMEM_BYTES>>>(H1, W2r, H2, 512,
                                                           b2, g2, bt2, m2, v2, 0);
    // max over 8 keyframes
    max_k_kernel<<<512, 512>>>(H2, (float*)d_out);
}

// round 17
// speedup vs baseline: 1.0753x; 1.0753x over previous
#include <cuda_runtime.h>
#include <stdint.h>
#include <math.h>

#define EPSF 1e-3f

// ---------------- scratch (allocation-free: __device__ globals) ----------------
__device__ __align__(1024) float g_imgT[64UL * 1600UL * 256UL];  // [F][H*W][C]
__device__ __align__(1024) float g_A  [4096UL * 12544UL];   // im2col  [R][bin*256+c], tf32-rounded
__device__ __align__(1024) float g_W1p[ 512UL * 12544UL];   // w1 perm [O][bin*256+c], tf32-rounded
__device__ __align__(1024) float g_W2r[ 512UL *   512UL];   // tf32-rounded w2
__device__ __align__(1024) float g_H1 [4096UL *   512UL];   // tf32-rounded FC1 out
__device__ __align__(1024) float g_H2 [4096UL *   512UL];

__device__ __forceinline__ float tf32r(float x) {
    uint32_t u;
    asm("cvt.rna.tf32.f32 %0, %1;" : "=r"(u) : "f"(x));
    return __uint_as_float(u);
}

// ------------------------------------------------------------------
// Transpose images [F,C,1600] -> [F,1600,C].
// ------------------------------------------------------------------
__global__ void transpose_img_kernel(const float* __restrict__ images) {
    __shared__ float tile[32][33];
    const int f   = blockIdx.z;
    const int hw0 = blockIdx.x * 32;
    const int c0  = blockIdx.y * 32;
    const float* src = images + (size_t)f * 256 * 1600;
    float*       dst = g_imgT + (size_t)f * 1600 * 256;

    #pragma unroll
    for (int i = 0; i < 4; ++i) {
        const int c = c0 + threadIdx.y + i * 8;
        tile[threadIdx.y + i * 8][threadIdx.x] = src[(size_t)c * 1600 + hw0 + threadIdx.x];
    }
    __syncthreads();
    #pragma unroll
    for (int i = 0; i < 4; ++i) {
        const int hw = hw0 + threadIdx.y + i * 8;
        dst[(size_t)hw * 256 + c0 + threadIdx.x] = tile[threadIdx.x][threadIdx.y + i * 8];
    }
}

// ------------------------------------------------------------------
// Permute + tf32-round w1 [O=512, C=256, 49] -> [O][bin*256+c]
// ------------------------------------------------------------------
__global__ void permute_w1_kernel(const float* __restrict__ w1) {
    __shared__ float buf[128 * 49];
    const int o  = blockIdx.x >> 1;
    const int c0 = (blockIdx.x & 1) * 128;
    const float* src = w1 + (size_t)o * 12544 + (size_t)c0 * 49;
    for (int i = threadIdx.x; i < 128 * 49; i += 256) buf[i] = src[i];
    __syncthreads();
    float* dst = g_W1p + (size_t)o * 12544;
    for (int i = threadIdx.x; i < 128 * 49; i += 256) {
        const int bin = i >> 7;
        const int cc  = i & 127;
        dst[bin * 256 + c0 + cc] = tf32r(buf[cc * 49 + bin]);
    }
}

__global__ void round_w2_kernel(const float* __restrict__ w2) {
    const int i = blockIdx.x * 256 + threadIdx.x;
    g_W2r[i] = tf32r(w2[i]);
}

// ------------------------------------------------------------------
// RoIAlign + im2col, 4 channels per thread (float4), 64 thr/block.
// ------------------------------------------------------------------
__global__ __launch_bounds__(64) void roi_im2col_kernel(const int*   __restrict__ kfi,
                                                        const float* __restrict__ boxes) {
    const int r  = blockIdx.x;
    const int c4 = threadIdx.x;          // channel quad 0..63

    const int f = kfi[r];
    const float x1 = boxes[r * 4 + 0] * 40.0f;
    const float y1 = boxes[r * 4 + 1] * 40.0f;
    const float x2 = boxes[r * 4 + 2] * 40.0f;
    const float y2 = boxes[r * 4 + 3] * 40.0f;
    const float bw = (x2 - x1) / 7.0f;
    const float bh = (y2 - y1) / 7.0f;

    const float4* __restrict__ img =
        (const float4*)(g_imgT + (size_t)f * 1600 * 256) + c4;
    float4* __restrict__ arow = (float4*)(g_A + (size_t)r * 12544) + c4;

    #pragma unroll 7
    for (int bin = 0; bin < 49; ++bin) {
        const int by = bin / 7;
        const int bx = bin - by * 7;
        const float X = x1 + ((float)bx + 0.5f) * bw;
        const float Y = y1 + ((float)by + 0.5f) * bh;
        const bool valid = (X > -1.0f) && (X < 40.0f) && (Y > -1.0f) && (Y < 40.0f);

        float x = fminf(fmaxf(X, 0.0f), 39.0f);
        float y = fminf(fmaxf(Y, 0.0f), 39.0f);
        const int x0 = (int)floorf(x);
        const int y0 = (int)floorf(y);
        const int x1i = min(x0 + 1, 39);
        const int y1i = min(y0 + 1, 39);
        const float lx = x - (float)x0;
        const float ly = y - (float)y0;

        float4 v = make_float4(0.0f, 0.0f, 0.0f, 0.0f);
        if (valid) {
            const float w00 = (1.0f - ly) * (1.0f - lx);
            const float w01 = (1.0f - ly) * lx;
            const float w10 = ly * (1.0f - lx);
            const float w11 = ly * lx;
            const float4 p00 = img[(size_t)(y0  * 40 + x0 ) * 64];
            const float4 p01 = img[(size_t)(y0  * 40 + x1i) * 64];
            const float4 p10 = img[(size_t)(y1i * 40 + x0 ) * 64];
            const float4 p11 = img[(size_t)(y1i * 40 + x1i) * 64];
            v.x = p00.x * w00 + p01.x * w01 + p10.x * w10 + p11.x * w11;
            v.y = p00.y * w00 + p01.y * w01 + p10.y * w10 + p11.y * w11;
            v.z = p00.z * w00 + p01.z * w01 + p10.z * w10 + p11.z * w11;
            v.w = p00.w * w00 + p01.w * w01 + p10.w * w10 + p11.w * w11;
        }
        arow[bin * 64] = make_float4(tf32r(v.x), tf32r(v.y), tf32r(v.z), tf32r(v.w));
    }
}

// ------------------------------------------------------------------
// tf32 mma.sync GEMM v6: BK=64 (halved per-ktile overhead count).
// BM=BN=128, BK=64, 256 threads (8 warps, 2x4), warp tile 64x32.
// 3-stage cp.async pipeline (64KB/stage, 193KB smem), LDSM frags.
// Rows are 256B (16 chunks); swizzle (cc&8)|((cc&7)^(m&7)).
// ------------------------------------------------------------------
#define STAGES 3
#define STAGE_FLOATS 16384               // A 8192 + B 8192
#define GEMM_SMEM_BYTES (STAGES * STAGE_FLOATS * 4 + 1024)   // 197632

__device__ __forceinline__ void cpasync16(uint32_t s, const float* g) {
    asm volatile("cp.async.cg.shared.global [%0], [%1], 16;" :: "r"(s), "l"(g) : "memory");
}
__device__ __forceinline__ void mma_tf32(float* d, const uint32_t* a, const uint32_t* b) {
    asm volatile("mma.sync.aligned.m16n8k8.row.col.f32.tf32.tf32.f32 "
                 "{%0,%1,%2,%3}, {%4,%5,%6,%7}, {%8,%9}, {%0,%1,%2,%3};"
                 : "+f"(d[0]), "+f"(d[1]), "+f"(d[2]), "+f"(d[3])
                 : "r"(a[0]), "r"(a[1]), "r"(a[2]), "r"(a[3]), "r"(b[0]), "r"(b[1]));
}
__device__ __forceinline__ void ldsm_x4(uint32_t* d, uint32_t addr) {
    asm volatile("ldmatrix.sync.aligned.m8n8.x4.shared.b16 {%0,%1,%2,%3}, [%4];"
                 : "=r"(d[0]), "=r"(d[1]), "=r"(d[2]), "=r"(d[3]) : "r"(addr));
}

__global__ __launch_bounds__(256, 1) void gemm_mma_kernel(
    const float* __restrict__ A, const float* __restrict__ B,
    float* __restrict__ C, int K,
    const float* __restrict__ bias,
    const float* __restrict__ gamma, const float* __restrict__ beta,
    const float* __restrict__ mean,  const float* __restrict__ var,
    int round_out)
{
    extern __shared__ float smem[];
    float* sarr = smem + STAGES * STAGE_FLOATS;
    float* oarr = sarr + 128;

    const int t    = threadIdx.x;
    const int lane = t & 31;
    const int wid  = t >> 5;
    const int mw   = wid & 1;          // 0..1 (M, x64)
    const int nw   = wid >> 1;         // 0..3 (N, x32)
    const int g    = lane >> 2;
    const int tig  = lane & 3;
    const int bm   = blockIdx.x * 128;
    const int bn   = blockIdx.y * 128;

    for (int c2 = t; c2 < 128; c2 += 256) {
        const int cg = bn + c2;
        const float s = gamma[cg] * rsqrtf(var[cg] + EPSF);
        sarr[c2] = s;
        oarr[c2] = (bias[cg] - mean[cg]) * s + beta[cg];
    }

    uint32_t sbase;
    asm("{ .reg .u64 t0; cvta.to.shared.u64 t0, %1; cvt.u32.u64 %0, t0; }"
        : "=r"(sbase) : "l"(smem));

    // ldmatrix per-lane addressing (256B rows, 16 chunks/row):
    const int rr   = lane & 7;
    const int rowa = mw * 64 + rr + ((lane >> 3) & 1) * 8;      // + mf*16
    const int qha  = (lane >> 4) & 1;
    const uint32_t aoff = (uint32_t)rowa * 256;
    const uint32_t swa  = (uint32_t)(rowa & 7);
    const int rowb = nw * 32 + rr + ((lane >> 4) & 1) * 8;      // + j*16
    const int qhb  = (lane >> 3) & 1;
    const uint32_t boff = (uint32_t)rowb * 256 + 8192 * 4;      // B after A (32 KB)
    const uint32_t swb  = (uint32_t)(rowb & 7);

    // cp.async chunk plan: 4096 chunks/stage (A 2048 + B 2048), 16/thread
    const float* aG[8]; uint32_t aS[8];
    const float* bG[8]; uint32_t bS[8];
    #pragma unroll
    for (int j = 0; j < 8; ++j) {
        const int id = t + j * 256;       // 0..2047
        const int m  = id >> 4;           // row 0..127
        const int cc = id & 15;           // chunk 0..15
        const uint32_t swz = (uint32_t)((cc & 8) | ((cc & 7) ^ (m & 7)));
        const uint32_t soff = (uint32_t)(m * 64 + swz * 4) * 4;
        aG[j] = A + (size_t)(bm + m) * K + cc * 4;
        bG[j] = B + (size_t)(bn + m) * K + cc * 4;
        aS[j] = soff;
        bS[j] = soff + 8192 * 4;
    }

    const int nkt = K >> 6;               // ktiles of 64

    // preload stages 0,1
    const int npre = nkt < 2 ? nkt : 2;
    for (int s = 0; s < npre; ++s) {
        const uint32_t stg = sbase + s * (STAGE_FLOATS * 4);
        #pragma unroll
        for (int j = 0; j < 8; ++j) {
            cpasync16(stg + aS[j], aG[j] + s * 64);
            cpasync16(stg + bS[j], bG[j] + s * 64);
        }
        asm volatile("cp.async.commit_group;" ::: "memory");
    }

    float acc[4][4][4];
    #pragma unroll
    for (int i = 0; i < 4; ++i)
        #pragma unroll
        for (int j = 0; j < 4; ++j)
            #pragma unroll
            for (int q = 0; q < 4; ++q) acc[i][j][q] = 0.0f;

    int st = 0;                           // stage of kt
    for (int kt = 0; kt < nkt; ++kt) {
        // all-but-newest pending -> group kt complete (commit is unconditional)
        asm volatile("cp.async.wait_group 1;" ::: "memory");
        __syncthreads();

        // prefetch kt+2 into the stage computed at kt-1 (safe after sync)
        const int kp = kt + 2;
        if (kp < nkt) {
            int sp = st + 2; if (sp >= STAGES) sp -= STAGES;
            const uint32_t stg = sbase + sp * (STAGE_FLOATS * 4);
            #pragma unroll
            for (int j = 0; j < 8; ++j) {
                cpasync16(stg + aS[j], aG[j] + kp * 64);
                cpasync16(stg + bS[j], bG[j] + kp * 64);
            }
        }
        asm volatile("cp.async.commit_group;" ::: "memory");

        const uint32_t sAb = sbase + st * (STAGE_FLOATS * 4);

        #pragma unroll
        for (int kk = 0; kk < 8; ++kk) {
            uint32_t afr[4][4], bfr[4][2];
            const uint32_t chA = (uint32_t)(2 * kk + qha);
            const uint32_t chB = (uint32_t)(2 * kk + qhb);
            const uint32_t ach = ((chA & 8) | ((chA & 7) ^ swa)) << 4;
            const uint32_t bch = ((chB & 8) | ((chB & 7) ^ swb)) << 4;
            #pragma unroll
            for (int mf = 0; mf < 4; ++mf)
                ldsm_x4(afr[mf], sAb + aoff + (uint32_t)mf * 4096 + ach);
            #pragma unroll
            for (int j = 0; j < 2; ++j) {
                uint32_t d4[4];
                ldsm_x4(d4, sAb + boff + (uint32_t)j * 4096 + bch);
                bfr[2 * j][0]     = d4[0];
                bfr[2 * j][1]     = d4[1];
                bfr[2 * j + 1][0] = d4[2];
                bfr[2 * j + 1][1] = d4[3];
            }
            #pragma unroll
            for (int mf = 0; mf < 4; ++mf)
                #pragma unroll
                for (int nf = 0; nf < 4; ++nf)
                    mma_tf32(acc[mf][nf], afr[mf], bfr[nf]);
        }
        if (++st == STAGES) st = 0;
    }

    // epilogue: bias+BN+ReLU (+optional tf32 rounding), float2 stores
    #pragma unroll
    for (int mf = 0; mf < 4; ++mf) {
        const int r0 = bm + mw * 64 + mf * 16 + g;
        #pragma unroll
        for (int nf = 0; nf < 4; ++nf) {
            const int cl = nw * 32 + nf * 8 + tig * 2;
            const float s0 = sarr[cl],     s1 = sarr[cl + 1];
            const float o0 = oarr[cl],     o1 = oarr[cl + 1];
            float v00 = fmaxf(acc[mf][nf][0] * s0 + o0, 0.0f);
            float v01 = fmaxf(acc[mf][nf][1] * s1 + o1, 0.0f);
            float v10 = fmaxf(acc[mf][nf][2] * s0 + o0, 0.0f);
            float v11 = fmaxf(acc[mf][nf][3] * s1 + o1, 0.0f);
            if (round_out) {
                v00 = tf32r(v00); v01 = tf32r(v01);
                v10 = tf32r(v10); v11 = tf32r(v11);
            }
            *(float2*)(C + (size_t)r0 * 512 + bn + cl)       = make_float2(v00, v01);
            *(float2*)(C + (size_t)(r0 + 8) * 512 + bn + cl) = make_float2(v10, v11);
        }
    }
}

// ------------------------------------------------------------------
// max over K=8 keyframes
// ------------------------------------------------------------------
__global__ void max_k_kernel(const float* __restrict__ H2, float* __restrict__ out) {
    const int n = blockIdx.x;
    const int d = threadIdx.x;
    const float* p = H2 + (size_t)n * 8 * 512 + d;
    float m = p[0];
    #pragma unroll
    for (int k = 1; k < 8; ++k) m = fmaxf(m, p[(size_t)k * 512]);
    out[(size_t)n * 512 + d] = m;
}

// ------------------------------------------------------------------
extern "C" void kernel_launch(void* const* d_in, const int* in_sizes, int n_in,
                              void* d_out, int out_size) {
    const float* images = (const float*)d_in[0];
    const int*   kfi    = (const int*)  d_in[1];
    const float* boxes  = (const float*)d_in[2];
    const float* w1     = (const float*)d_in[3];
    const float* b1     = (const float*)d_in[4];
    const float* g1     = (const float*)d_in[5];
    const float* bt1    = (const float*)d_in[6];
    const float* m1     = (const float*)d_in[7];
    const float* v1     = (const float*)d_in[8];
    const float* w2     = (const float*)d_in[9];
    const float* b2     = (const float*)d_in[10];
    const float* g2     = (const float*)d_in[11];
    const float* bt2    = (const float*)d_in[12];
    const float* m2     = (const float*)d_in[13];
    const float* v2     = (const float*)d_in[14];

    float *A, *W1p, *W2r, *H1, *H2;
    cudaGetSymbolAddress((void**)&A,   g_A);
    cudaGetSymbolAddress((void**)&W1p, g_W1p);
    cudaGetSymbolAddress((void**)&W2r, g_W2r);
    cudaGetSymbolAddress((void**)&H1,  g_H1);
    cudaGetSymbolAddress((void**)&H2,  g_H2);

    cudaFuncSetAttribute(gemm_mma_kernel, cudaFuncAttributeMaxDynamicSharedMemorySize,
                         GEMM_SMEM_BYTES);

    // prep (independent, cheap)
    transpose_img_kernel<<<dim3(50, 8, 64), dim3(32, 8)>>>(images);
    permute_w1_kernel<<<1024, 256>>>(w1);
    round_w2_kernel<<<1024, 256>>>(w2);

    // roi-align im2col from channel-last layout
    roi_im2col_kernel<<<4096, 64>>>(kfi, boxes);

    // FC1
    gemm_mma_kernel<<<dim3(32, 4), 256, GEMM_SMEM_BYTES>>>(A, W1p, H1, 12544,
                                                           b1, g1, bt1, m1, v1, 1);
    // FC2
    gemm_mma_kernel<<<dim3(32, 4), 256, GEMM_SMEM_BYTES>>>(H1, W2r, H2, 512,
                                                           b2, g2, bt2, m2, v2, 0);
    // max over 8 keyframes
    max_k_kernel<<<512, 512>>>(H2, (float*)d_out);
}